// round 6
// baseline (speedup 1.0000x reference)
#include <cuda_runtime.h>
#include <cuda_fp16.h>
#include <math.h>
#include <stdint.h>

#define T_STEPS 256
#define BATCH   256
#define IN_DIM  512
#define H_DIM   512
#define GATES   2048

// ---------------- device scratch -------------------------------------------
__device__ float    g_Xg[(size_t)T_STEPS * BATCH * GATES];   // x@Wih^T + b
__device__ float    g_Wp_ih[64 * 2048 * 8];                  // tf32 frags (xgemm)
__device__ unsigned g_Wph[16 * 4 * 4 * 32 * 32 * 2];         // fp16 W_hh frags (2MB)
__device__ unsigned g_APg[2 * 8 * 32 * 2 * 32 * 4];          // fp16 h frags, dbl-buf
__device__ unsigned g_cnt[8 * 32];                           // per-group barrier
__device__ volatile unsigned g_gen[8 * 32];

// ---------------- helpers --------------------------------------------------
__device__ __forceinline__ float f2tf32f(float f) {
    unsigned r;
    asm("cvt.rna.tf32.f32 %0, %1;" : "=r"(r) : "f"(f));
    return __uint_as_float(r);
}

__device__ __forceinline__ void mma_tf32(float* c,
    unsigned a0, unsigned a1, unsigned a2, unsigned a3,
    unsigned b0, unsigned b1)
{
    asm volatile(
        "mma.sync.aligned.m16n8k8.row.col.f32.tf32.tf32.f32 "
        "{%0,%1,%2,%3},{%4,%5,%6,%7},{%8,%9},{%0,%1,%2,%3};"
        : "+f"(c[0]), "+f"(c[1]), "+f"(c[2]), "+f"(c[3])
        : "r"(a0), "r"(a1), "r"(a2), "r"(a3), "r"(b0), "r"(b1));
}

__device__ __forceinline__ void mma_f16(float* c, uint4 A, uint2 B) {
    asm volatile(
        "mma.sync.aligned.m16n8k16.row.col.f32.f16.f16.f32 "
        "{%0,%1,%2,%3},{%4,%5,%6,%7},{%8,%9},{%0,%1,%2,%3};"
        : "+f"(c[0]), "+f"(c[1]), "+f"(c[2]), "+f"(c[3])
        : "r"(A.x), "r"(A.y), "r"(A.z), "r"(A.w), "r"(B.x), "r"(B.y));
}

__device__ __forceinline__ float sigm(float v) { return 1.0f / (1.0f + expf(-v)); }

// ---------------- prep: tf32 frags for Wih (xgemm path) -------------------
__global__ void prep_ih(const float* __restrict__ Wih) {
    int idx = blockIdx.x * blockDim.x + threadIdx.x;   // < 2^20
    int n = idx >> 9, k = idx & 511;
    int kb = k >> 3, p = k & 3, hi = (k >> 2) & 1;
    g_Wp_ih[(((size_t)kb * 2048 + n) * 4 + p) * 2 + hi] = f2tf32f(Wih[idx]);
}

// ---------------- prep: fp16 B-fragments for W_hh -------------------------
// frag value at (k,n) = Whh[n][k]; layout [ht][g][hg][kb16][lane][reg] (b32)
__global__ void prep_hh(const float* __restrict__ Whh) {
    int t = blockIdx.x * blockDim.x + threadIdx.x;     // < 2^19
    int n = t >> 8, kp = t & 255, k = kp * 2;
    float2 wv = ((const float2*)Whh)[(size_t)n * 256 + kp];
    __half2 h2 = __floats2half2_rn(wv.x, wv.y);        // low = even k
    int g  = n >> 9, hh = n & 511;
    int ht = hh >> 5, hg = (hh >> 3) & 3;
    int kb16 = k >> 4;
    int lanei = ((n & 7) << 2) | ((k & 7) >> 1);
    int reg = (k >> 3) & 1;
    size_t bi = ((((size_t)(ht * 4 + g) * 4 + hg) * 32 + kb16) * 32 + lanei) * 2 + reg;
    g_Wph[bi] = *(unsigned*)&h2;
}

// ---------------- xgemm (unchanged tf32 path) ------------------------------
#define AP_WORDS (64 * 32 * 12)
extern __shared__ float sm_dyn[];

template <bool ZERO>
__device__ __forceinline__ void stage_A_x(float* Ap, const float* src_row, int tid) {
    int b  = tid >> 3;
    int kc = tid & 7;
    const float4* src = (const float4*)(src_row + kc * 64);
    #pragma unroll
    for (int v = 0; v < 16; v++) {
        float4 hv = ZERO ? make_float4(0.f,0.f,0.f,0.f) : __ldg(src + v);
        float vals[4] = {hv.x, hv.y, hv.z, hv.w};
        int kbase = kc * 64 + v * 4;
        #pragma unroll
        for (int e = 0; e < 4; e++) {
            int k = kbase + e;
            int kb = k >> 3;
            int l  = ((b & 7) << 2) | (k & 3);
            int j  = ((b >> 4) << 2) | (((k >> 2) & 1) << 1) | ((b >> 3) & 1);
            Ap[(kb * 32 + l) * 12 + j] = f2tf32f(vals[e]);
        }
    }
}

__global__ __launch_bounds__(256, 2) void xgemm_tc(
    const float* __restrict__ x,
    const float* __restrict__ bih,
    const float* __restrict__ bhh)
{
    float* Ap = sm_dyn;
    const int tid = threadIdx.x, lane = tid & 31, w = tid >> 5;
    const int n0 = blockIdx.x * 128;
    const int m0 = blockIdx.y * 32;

    stage_A_x<false>(Ap, x + (size_t)(m0 + (tid >> 3)) * IN_DIM, tid);
    __syncthreads();

    float acc[2][2][4] = {};
    const int nw = n0 + w * 16;
    const float2* Wp = (const float2*)g_Wp_ih;

    #pragma unroll 4
    for (int kb = 0; kb < 64; kb++) {
        float4 A0 = *(float4*)&Ap[(kb * 32 + lane) * 12];
        float4 A1 = *(float4*)&Ap[(kb * 32 + lane) * 12 + 4];
        unsigned a0x = __float_as_uint(A0.x), a0y = __float_as_uint(A0.y);
        unsigned a0z = __float_as_uint(A0.z), a0w = __float_as_uint(A0.w);
        unsigned a1x = __float_as_uint(A1.x), a1y = __float_as_uint(A1.y);
        unsigned a1z = __float_as_uint(A1.z), a1w = __float_as_uint(A1.w);
        #pragma unroll
        for (int nt = 0; nt < 2; nt++) {
            int n = nw + nt * 8 + (lane >> 2);
            float2 bv = Wp[((size_t)kb * 2048 + n) * 4 + (lane & 3)];
            unsigned b0 = __float_as_uint(bv.x), b1 = __float_as_uint(bv.y);
            mma_tf32(acc[0][nt], a0x, a0y, a0z, a0w, b0, b1);
            mma_tf32(acc[1][nt], a1x, a1y, a1z, a1w, b0, b1);
        }
    }

    #pragma unroll
    for (int nt = 0; nt < 2; nt++) {
        int nc = nw + nt * 8 + (lane & 3) * 2;
        float bs0 = __ldg(&bih[nc]) + __ldg(&bhh[nc]);
        float bs1 = __ldg(&bih[nc + 1]) + __ldg(&bhh[nc + 1]);
        #pragma unroll
        for (int mt = 0; mt < 2; mt++) {
            int r0 = m0 + mt * 16 + (lane >> 2);
            float2 v0 = make_float2(acc[mt][nt][0] + bs0, acc[mt][nt][1] + bs1);
            float2 v1 = make_float2(acc[mt][nt][2] + bs0, acc[mt][nt][3] + bs1);
            __stcs((float2*)&g_Xg[(size_t)r0 * GATES + nc], v0);
            __stcs((float2*)&g_Xg[(size_t)(r0 + 8) * GATES + nc], v1);
        }
    }
}

// ---------------- per-group barrier (16 blocks sharing a b-tile) -----------
__device__ __forceinline__ void group_sync(int grp) {
    __threadfence();                 // make this thread's STGs L2-visible
    __syncthreads();
    if (threadIdx.x == 0) {
        unsigned snap = g_gen[grp * 32];
        if (atomicAdd(&g_cnt[grp * 32], 1u) == 15u) {
            g_cnt[grp * 32] = 0;
            __threadfence();
            g_gen[grp * 32] = snap + 1;
        } else {
            while (g_gen[grp * 32] == snap) __nanosleep(20);
        }
    }
    __syncthreads();
}

// ---------------- persistent LSTM recurrence (fp16 MMA, W in smem) ---------
// 128 blocks = 8 b-groups x 16 hh-tiles. Block tile: 32 b x 32 hh x 4 gates.
// W_hh slice (128KB fp16 frags) resident in smem for the whole kernel.
// h exchanged as pre-packed fp16 A-fragments via L2 (32KB copy/step/block).
__global__ __launch_bounds__(256, 1) void lstm_tc(
    const int*  __restrict__ dones,
    float* __restrict__ out_lstm,       // [T,B,H]
    float* __restrict__ out_hidden)     // [T,2,B,H]
{
    unsigned* Ws  = (unsigned*)sm_dyn;          // 32768 u32 (128KB)
    unsigned* APs = Ws + 32768;                 // 8192 u32  (32KB)
    float*    Acc = (float*)(APs + 8192);       // 4608 f32  (18KB)

    const int tid = threadIdx.x, lane = tid & 31, w = tid >> 5;
    const int ht = blockIdx.x & 15, bt = blockIdx.x >> 4;
    const int hh0 = ht * 32, b0 = bt * 32;
    const int gp = w >> 2, hg = w & 3;
    const int eb  = tid >> 3;          // epilogue batch row 0..31
    const int ehh = (tid & 7) * 4;     // epilogue 4 consecutive hh

    // load W slice into smem once (verbatim fragment copy)
    {
        const uint4* src = (const uint4*)(g_Wph + (size_t)ht * 32768);
        uint4* dst = (uint4*)Ws;
        #pragma unroll
        for (int i = 0; i < 32; i++) dst[tid + i * 256] = src[tid + i * 256];
    }
    __syncthreads();

    float h_st[4] = {0.f,0.f,0.f,0.f};
    float c_st[4] = {0.f,0.f,0.f,0.f};

    for (int st = 0; st < T_STEPS; st++) {
        // prefetch Xg + done mask (overlaps with k-loop)
        float4 xv[4];
        const float* xg = g_Xg + ((size_t)st * BATCH + (b0 + eb)) * GATES + hh0 + ehh;
        #pragma unroll
        for (int g = 0; g < 4; g++) xv[g] = __ldcs((const float4*)(xg + g * H_DIM));
        const float keep = 1.0f - (float)__ldg(&dones[st * BATCH + b0 + eb]);

        float4 ag[4];
        if (st == 0) {
            #pragma unroll
            for (int g = 0; g < 4; g++) ag[g] = make_float4(0.f,0.f,0.f,0.f);
        } else {
            // copy A fragments (32KB) from L2 into smem
            const uint4* asrc = (const uint4*)(g_APg + ((size_t)(st & 1) * 8 + bt) * 8192);
            uint4* adst = (uint4*)APs;
            #pragma unroll
            for (int i = 0; i < 8; i++)
                adst[tid + i * 256] = __ldcg(asrc + tid + i * 256);
            __syncthreads();

            float acc[2][2][4] = {};       // [gi][mt][creg]
            #pragma unroll 4
            for (int kb = 0; kb < 32; kb++) {
                uint4 A0 = *(const uint4*)&APs[((kb * 2 + 0) * 32 + lane) * 4];
                uint4 A1 = *(const uint4*)&APs[((kb * 2 + 1) * 32 + lane) * 4];
                #pragma unroll
                for (int gi = 0; gi < 2; gi++) {
                    int nb = (gp * 2 + gi) * 4 + hg;
                    uint2 B = *(const uint2*)&Ws[((nb * 32 + kb) * 32 + lane) * 2];
                    mma_f16(acc[gi][0], A0, B);
                    mma_f16(acc[gi][1], A1, B);
                }
            }

            // exchange accumulators so each thread gets all 4 gates
            #pragma unroll
            for (int gi = 0; gi < 2; gi++) {
                int g  = gp * 2 + gi;
                int hc = hg * 8 + (lane & 3) * 2;
                #pragma unroll
                for (int mt = 0; mt < 2; mt++) {
                    int bl = mt * 16 + (lane >> 2);
                    *(float2*)&Acc[(g * 32 + bl) * 36 + hc] =
                        make_float2(acc[gi][mt][0], acc[gi][mt][1]);
                    *(float2*)&Acc[(g * 32 + bl + 8) * 36 + hc] =
                        make_float2(acc[gi][mt][2], acc[gi][mt][3]);
                }
            }
            __syncthreads();
            #pragma unroll
            for (int g = 0; g < 4; g++)
                ag[g] = *(const float4*)&Acc[(g * 32 + eb) * 36 + ehh];
        }

        // epilogue: gates -> state update; state lives in registers
        float4 hp4, cp4, hn4;
        float* hpf = &hp4.x; float* cpf = &cp4.x; float* hnf = &hn4.x;
        #pragma unroll
        for (int i = 0; i < 4; i++) {
            float gv_i = ((float*)&ag[0])[i] + ((float*)&xv[0])[i];
            float gv_f = ((float*)&ag[1])[i] + ((float*)&xv[1])[i];
            float gv_g = ((float*)&ag[2])[i] + ((float*)&xv[2])[i];
            float gv_o = ((float*)&ag[3])[i] + ((float*)&xv[3])[i];

            float hpv = h_st[i] * keep;
            float cpv = c_st[i] * keep;

            float ii = sigm(gv_i);
            float ff = sigm(gv_f);
            float gg = tanhf(gv_g);
            float oo = sigm(gv_o);

            float cnv = ff * cpv + ii * gg;
            float hnv = oo * tanhf(cnv);

            h_st[i] = hnv; c_st[i] = cnv;
            hpf[i] = hpv; cpf[i] = cpv; hnf[i] = hnv;
        }

        const size_t ob = (size_t)(b0 + eb) * H_DIM + hh0 + ehh;
        __stcs((float4*)&out_hidden[(size_t)(st * 2 + 0) * BATCH * H_DIM + ob], hp4);
        __stcs((float4*)&out_hidden[(size_t)(st * 2 + 1) * BATCH * H_DIM + ob], cp4);
        __stcs((float4*)&out_lstm  [(size_t)st * BATCH * H_DIM + ob],           hn4);

        if (st < T_STEPS - 1) {
            // store h*keep(st+1) as fp16 A-fragments for next step
            float kn = 1.0f - (float)__ldg(&dones[(st + 1) * BATCH + b0 + eb]);
            __half2 w0 = __floats2half2_rn(h_st[0] * kn, h_st[1] * kn);
            __half2 w1 = __floats2half2_rn(h_st[2] * kn, h_st[3] * kn);
            int k0   = hh0 + ehh;
            int kb16 = k0 >> 4;
            int mt   = eb >> 4;
            int reg  = ((eb >> 3) & 1) + (((k0 >> 3) & 1) << 1);
            int l0   = ((eb & 7) << 2) | ((k0 >> 1) & 3);
            unsigned* apd = g_APg +
                ((((size_t)((st + 1) & 1) * 8 + bt) * 32 + kb16) * 2 + mt) * 128;
            apd[l0 * 4 + reg]       = *(unsigned*)&w0;
            apd[(l0 + 1) * 4 + reg] = *(unsigned*)&w1;

            group_sync(bt);
        }
    }
}

// ---------------- launch ----------------------------------------------------
extern "C" void kernel_launch(void* const* d_in, const int* in_sizes, int n_in,
                              void* d_out, int out_size) {
    const float* x     = (const float*)d_in[0];
    const int*   dones = (const int*)  d_in[1];
    const float* Wih   = (const float*)d_in[2];
    const float* Whh   = (const float*)d_in[3];
    const float* bih   = (const float*)d_in[4];
    const float* bhh   = (const float*)d_in[5];

    float* out_lstm   = (float*)d_out;
    float* out_hidden = out_lstm + (size_t)T_STEPS * BATCH * H_DIM;

    const int smem_xg   = AP_WORDS * 4;                       // 98304 B
    const int smem_lstm = (32768 + 8192 + 4608) * 4;          // 182272 B
    cudaFuncSetAttribute(xgemm_tc, cudaFuncAttributeMaxDynamicSharedMemorySize,
                         smem_xg);
    cudaFuncSetAttribute(lstm_tc, cudaFuncAttributeMaxDynamicSharedMemorySize,
                         smem_lstm);

    prep_ih<<<4096, 256>>>(Wih);
    prep_hh<<<2048, 256>>>(Whh);

    dim3 gx(GATES / 128, (T_STEPS * BATCH) / 32);             // (16, 2048)
    xgemm_tc<<<gx, 256, smem_xg>>>(x, bih, bhh);

    lstm_tc<<<128, 256, smem_lstm>>>(dones, out_lstm, out_hidden);
}

// round 7
// speedup vs baseline: 1.0184x; 1.0184x over previous
#include <cuda_runtime.h>
#include <cuda_fp16.h>
#include <math.h>
#include <stdint.h>

#define T_STEPS 256
#define BATCH   256
#define IN_DIM  512
#define H_DIM   512
#define GATES   2048

// ---------------- device scratch -------------------------------------------
__device__ float    g_Xg[(size_t)T_STEPS * BATCH * GATES];   // x@Wih^T + b
__device__ float    g_Wp_ih[64 * 2048 * 8];                  // tf32 frags (xgemm)
__device__ unsigned g_Wph[16 * 4 * 4 * 32 * 32 * 2];         // fp16 W_hh frags (2MB)
__device__ unsigned g_APg[2 * 8 * 32 * 2 * 32 * 4];          // fp16 h frags, dbl-buf
__device__ unsigned g_cnt[8 * 32];                           // per-group barrier
__device__ unsigned g_gen[8 * 32];

// ---------------- helpers --------------------------------------------------
__device__ __forceinline__ float f2tf32f(float f) {
    unsigned r;
    asm("cvt.rna.tf32.f32 %0, %1;" : "=r"(r) : "f"(f));
    return __uint_as_float(r);
}

__device__ __forceinline__ void mma_tf32(float* c,
    unsigned a0, unsigned a1, unsigned a2, unsigned a3,
    unsigned b0, unsigned b1)
{
    asm volatile(
        "mma.sync.aligned.m16n8k8.row.col.f32.tf32.tf32.f32 "
        "{%0,%1,%2,%3},{%4,%5,%6,%7},{%8,%9},{%0,%1,%2,%3};"
        : "+f"(c[0]), "+f"(c[1]), "+f"(c[2]), "+f"(c[3])
        : "r"(a0), "r"(a1), "r"(a2), "r"(a3), "r"(b0), "r"(b1));
}

__device__ __forceinline__ void mma_f16(float* c, uint4 A, uint2 B) {
    asm volatile(
        "mma.sync.aligned.m16n8k16.row.col.f32.f16.f16.f32 "
        "{%0,%1,%2,%3},{%4,%5,%6,%7},{%8,%9},{%0,%1,%2,%3};"
        : "+f"(c[0]), "+f"(c[1]), "+f"(c[2]), "+f"(c[3])
        : "r"(A.x), "r"(A.y), "r"(A.z), "r"(A.w), "r"(B.x), "r"(B.y));
}

__device__ __forceinline__ float sigm(float v) { return 1.0f / (1.0f + expf(-v)); }

__device__ __forceinline__ unsigned atom_add_acqrel(unsigned* p, unsigned v) {
    unsigned o;
    asm volatile("atom.acq_rel.gpu.global.add.u32 %0, [%1], %2;"
                 : "=r"(o) : "l"(p), "r"(v) : "memory");
    return o;
}
__device__ __forceinline__ void st_release(unsigned* p, unsigned v) {
    asm volatile("st.release.gpu.global.u32 [%0], %1;" :: "l"(p), "r"(v) : "memory");
}
__device__ __forceinline__ unsigned ld_acquire(const unsigned* p) {
    unsigned v;
    asm volatile("ld.acquire.gpu.global.u32 %0, [%1];" : "=r"(v) : "l"(p) : "memory");
    return v;
}

// ---------------- prep: tf32 frags for Wih (xgemm path) -------------------
__global__ void prep_ih(const float* __restrict__ Wih) {
    int idx = blockIdx.x * blockDim.x + threadIdx.x;   // < 2^20
    int n = idx >> 9, k = idx & 511;
    int kb = k >> 3, p = k & 3, hi = (k >> 2) & 1;
    g_Wp_ih[(((size_t)kb * 2048 + n) * 4 + p) * 2 + hi] = f2tf32f(Wih[idx]);
}

// ---------------- prep: fp16 B-fragments for W_hh -------------------------
// frag value at (k,n) = Whh[n][k]; layout [ht][g][hg][kb16][lane][reg] (b32)
__global__ void prep_hh(const float* __restrict__ Whh) {
    int t = blockIdx.x * blockDim.x + threadIdx.x;     // < 2^19
    int n = t >> 8, kp = t & 255, k = kp * 2;
    float2 wv = ((const float2*)Whh)[(size_t)n * 256 + kp];
    __half2 h2 = __floats2half2_rn(wv.x, wv.y);        // low = even k
    int g  = n >> 9, hh = n & 511;
    int ht = hh >> 5, hg = (hh >> 3) & 3;
    int kb16 = k >> 4;
    int lanei = ((n & 7) << 2) | ((k & 7) >> 1);
    int reg = (k >> 3) & 1;
    size_t bi = ((((size_t)(ht * 4 + g) * 4 + hg) * 32 + kb16) * 32 + lanei) * 2 + reg;
    g_Wph[bi] = *(unsigned*)&h2;
}

// ---------------- xgemm (tf32 MMA) -----------------------------------------
#define AP_WORDS (64 * 32 * 12)
extern __shared__ float sm_dyn[];

__device__ __forceinline__ void stage_A_x(float* Ap, const float* src_row, int tid) {
    int b  = tid >> 3;
    int kc = tid & 7;
    const float4* src = (const float4*)(src_row + kc * 64);
    #pragma unroll
    for (int v = 0; v < 16; v++) {
        float4 hv = __ldg(src + v);
        float vals[4] = {hv.x, hv.y, hv.z, hv.w};
        int kbase = kc * 64 + v * 4;
        #pragma unroll
        for (int e = 0; e < 4; e++) {
            int k = kbase + e;
            int kb = k >> 3;
            int l  = ((b & 7) << 2) | (k & 3);
            int j  = ((b >> 4) << 2) | (((k >> 2) & 1) << 1) | ((b >> 3) & 1);
            Ap[(kb * 32 + l) * 12 + j] = f2tf32f(vals[e]);
        }
    }
}

__global__ __launch_bounds__(256, 2) void xgemm_tc(
    const float* __restrict__ x,
    const float* __restrict__ bih,
    const float* __restrict__ bhh)
{
    float* Ap = sm_dyn;
    const int tid = threadIdx.x, lane = tid & 31, w = tid >> 5;
    const int n0 = blockIdx.x * 128;
    const int m0 = blockIdx.y * 32;

    stage_A_x(Ap, x + (size_t)(m0 + (tid >> 3)) * IN_DIM, tid);
    __syncthreads();

    float acc[2][2][4] = {};
    const int nw = n0 + w * 16;
    const float2* Wp = (const float2*)g_Wp_ih;

    #pragma unroll 4
    for (int kb = 0; kb < 64; kb++) {
        float4 A0 = *(float4*)&Ap[(kb * 32 + lane) * 12];
        float4 A1 = *(float4*)&Ap[(kb * 32 + lane) * 12 + 4];
        unsigned a0x = __float_as_uint(A0.x), a0y = __float_as_uint(A0.y);
        unsigned a0z = __float_as_uint(A0.z), a0w = __float_as_uint(A0.w);
        unsigned a1x = __float_as_uint(A1.x), a1y = __float_as_uint(A1.y);
        unsigned a1z = __float_as_uint(A1.z), a1w = __float_as_uint(A1.w);
        #pragma unroll
        for (int nt = 0; nt < 2; nt++) {
            int n = nw + nt * 8 + (lane >> 2);
            float2 bv = Wp[((size_t)kb * 2048 + n) * 4 + (lane & 3)];
            unsigned b0 = __float_as_uint(bv.x), b1 = __float_as_uint(bv.y);
            mma_tf32(acc[0][nt], a0x, a0y, a0z, a0w, b0, b1);
            mma_tf32(acc[1][nt], a1x, a1y, a1z, a1w, b0, b1);
        }
    }

    #pragma unroll
    for (int nt = 0; nt < 2; nt++) {
        int nc = nw + nt * 8 + (lane & 3) * 2;
        float bs0 = __ldg(&bih[nc]) + __ldg(&bhh[nc]);
        float bs1 = __ldg(&bih[nc + 1]) + __ldg(&bhh[nc + 1]);
        #pragma unroll
        for (int mt = 0; mt < 2; mt++) {
            int r0 = m0 + mt * 16 + (lane >> 2);
            float2 v0 = make_float2(acc[mt][nt][0] + bs0, acc[mt][nt][1] + bs1);
            float2 v1 = make_float2(acc[mt][nt][2] + bs0, acc[mt][nt][3] + bs1);
            __stcs((float2*)&g_Xg[(size_t)r0 * GATES + nc], v0);
            __stcs((float2*)&g_Xg[(size_t)(r0 + 8) * GATES + nc], v1);
        }
    }
}

// ---------------- persistent LSTM recurrence --------------------------------
// 128 blocks = 8 b-groups x 16 hh-tiles. Block tile: 32 b x 32 hh x 4 gates.
// warp w -> (m-half mh=w>>2, hh-octet hg=w&3), computing ALL 4 gates: MMA
// fragment ownership == epilogue ownership (no accumulator exchange).
// W_hh slice (128KB fp16 frags) resident in smem; h exchanged as pre-packed
// fp16 A-fragments via L2 with a release/acquire per-group barrier.
__global__ __launch_bounds__(256, 1) void lstm_tc(
    const int*  __restrict__ dones,
    float* __restrict__ out_lstm,       // [T,B,H]
    float* __restrict__ out_hidden)     // [T,2,B,H]
{
    unsigned* Ws  = (unsigned*)sm_dyn;          // 32768 u32 (128KB)
    unsigned* APs = Ws + 32768;                 // 8192 u32  (32KB)
    unsigned* Stg = APs + 8192;                 // 512 u32   (2KB)

    const int tid = threadIdx.x, lane = tid & 31, w = tid >> 5;
    const int ht = blockIdx.x & 15, bt = blockIdx.x >> 4;
    const int hh0 = ht * 32, b0 = bt * 32;
    const int mh = w >> 2, hg = w & 3;

    const int r0 = b0 + mh * 16 + (lane >> 2);      // batch rows r0, r0+8
    const int r1 = r0 + 8;
    const int c0 = hh0 + hg * 8 + (lane & 3) * 2;   // hh column (even)

    // load W slice into smem once (verbatim fragment copy)
    {
        const uint4* src = (const uint4*)(g_Wph + (size_t)ht * 32768);
        uint4* dst = (uint4*)Ws;
        #pragma unroll
        for (int i = 0; i < 32; i++) dst[tid + i * 256] = src[tid + i * 256];
    }
    __syncthreads();

    unsigned* cnt = &g_cnt[bt * 32];
    unsigned* gen = &g_gen[bt * 32];
    const unsigned gbase = ld_acquire(gen);   // survives graph replays

    // this thread's staging slot: kb16-local = hg>>1, mt = mh, lane, reg base
    const int slot = (((hg >> 1) * 2 + mh) * 128) + lane * 4 + ((hg & 1) << 1);

    float h_st[4] = {0.f,0.f,0.f,0.f};
    float c_st[4] = {0.f,0.f,0.f,0.f};
    float keep0 = 1.0f - (float)__ldg(&dones[r0]);
    float keep1 = 1.0f - (float)__ldg(&dones[r1]);

    for (int st = 0; st < T_STEPS; st++) {
        // prefetch Xg for this thread's 4 elements x 4 gates
        const float* xgr0 = g_Xg + ((size_t)st * BATCH + r0) * GATES + c0;
        const float* xgr1 = g_Xg + ((size_t)st * BATCH + r1) * GATES + c0;
        float2 xv0[4], xv1[4];
        #pragma unroll
        for (int g = 0; g < 4; g++) {
            xv0[g] = __ldcs((const float2*)(xgr0 + g * H_DIM));
            xv1[g] = __ldcs((const float2*)(xgr1 + g * H_DIM));
        }

        float acc[4][4] = {};
        if (st > 0) {
            // copy A fragments (32KB) from L2 into smem
            const uint4* asrc = (const uint4*)(g_APg + ((size_t)(st & 1) * 8 + bt) * 8192);
            uint4* adst = (uint4*)APs;
            #pragma unroll
            for (int i = 0; i < 8; i++)
                adst[tid + i * 256] = __ldcg(asrc + tid + i * 256);
            __syncthreads();

            #pragma unroll 4
            for (int kb = 0; kb < 32; kb++) {
                uint4 A = *(const uint4*)&APs[((kb * 2 + mh) * 32 + lane) * 4];
                #pragma unroll
                for (int g = 0; g < 4; g++) {
                    uint2 B = *(const uint2*)&Ws[(((g * 4 + hg) * 32 + kb) * 32 + lane) * 2];
                    mma_f16(acc[g], A, B);
                }
            }
        }

        // epilogue: 4 elements (r0,c0),(r0,c0+1),(r1,c0),(r1,c0+1)
        float xa[4][4];
        #pragma unroll
        for (int g = 0; g < 4; g++) {
            xa[g][0] = xv0[g].x; xa[g][1] = xv0[g].y;
            xa[g][2] = xv1[g].x; xa[g][3] = xv1[g].y;
        }
        float hp[4], cp[4];
        #pragma unroll
        for (int i = 0; i < 4; i++) {
            float k_ = (i < 2) ? keep0 : keep1;
            float hpv = h_st[i] * k_;
            float cpv = c_st[i] * k_;
            float ii = sigm(acc[0][i] + xa[0][i]);
            float ff = sigm(acc[1][i] + xa[1][i]);
            float gg = tanhf(acc[2][i] + xa[2][i]);
            float oo = sigm(acc[3][i] + xa[3][i]);
            float cn = ff * cpv + ii * gg;
            float hn = oo * tanhf(cn);
            h_st[i] = hn; c_st[i] = cn; hp[i] = hpv; cp[i] = cpv;
        }

        bool not_last = (st < T_STEPS - 1);
        unsigned tgt = gbase + (unsigned)st + 1u;
        if (not_last) {
            // stage next-step h (pre-masked) as fp16 frags, coalesced flush
            float kn0 = 1.0f - (float)__ldg(&dones[(st + 1) * BATCH + r0]);
            float kn1 = 1.0f - (float)__ldg(&dones[(st + 1) * BATCH + r1]);
            __half2 w0 = __floats2half2_rn(h_st[0] * kn0, h_st[1] * kn0);
            __half2 w1 = __floats2half2_rn(h_st[2] * kn1, h_st[3] * kn1);
            Stg[slot]     = *(unsigned*)&w0;
            Stg[slot + 1] = *(unsigned*)&w1;
            keep0 = kn0; keep1 = kn1;
            __syncthreads();
            unsigned* apd = g_APg + (((size_t)((st + 1) & 1) * 8 + bt) * 8192)
                          + (size_t)ht * 512;
            if (tid < 128)
                ((uint4*)apd)[tid] = ((const uint4*)Stg)[tid];
            __syncthreads();
            if (tid == 0) {
                if (atom_add_acqrel(cnt, 1u) == 15u) {
                    *cnt = 0;                 // ordered before release below
                    st_release(gen, tgt);
                }
            }
        }

        // outputs (drain while thread0 spins)
        const size_t ob0 = (size_t)r0 * H_DIM + c0;
        const size_t ob1 = (size_t)r1 * H_DIM + c0;
        const size_t hb  = (size_t)st * 2 * BATCH * H_DIM;
        const size_t lb  = (size_t)st * BATCH * H_DIM;
        __stcs((float2*)&out_hidden[hb + ob0],                     make_float2(hp[0], hp[1]));
        __stcs((float2*)&out_hidden[hb + ob1],                     make_float2(hp[2], hp[3]));
        __stcs((float2*)&out_hidden[hb + (size_t)BATCH*H_DIM + ob0], make_float2(cp[0], cp[1]));
        __stcs((float2*)&out_hidden[hb + (size_t)BATCH*H_DIM + ob1], make_float2(cp[2], cp[3]));
        __stcs((float2*)&out_lstm[lb + ob0],                       make_float2(h_st[0], h_st[1]));
        __stcs((float2*)&out_lstm[lb + ob1],                       make_float2(h_st[2], h_st[3]));

        if (not_last) {
            if (tid == 0) {
                while (ld_acquire(gen) != tgt) { }
            }
            __syncthreads();
        }
    }
}

// ---------------- launch ----------------------------------------------------
extern "C" void kernel_launch(void* const* d_in, const int* in_sizes, int n_in,
                              void* d_out, int out_size) {
    const float* x     = (const float*)d_in[0];
    const int*   dones = (const int*)  d_in[1];
    const float* Wih   = (const float*)d_in[2];
    const float* Whh   = (const float*)d_in[3];
    const float* bih   = (const float*)d_in[4];
    const float* bhh   = (const float*)d_in[5];

    float* out_lstm   = (float*)d_out;
    float* out_hidden = out_lstm + (size_t)T_STEPS * BATCH * H_DIM;

    const int smem_xg   = AP_WORDS * 4;                       // 98304 B
    const int smem_lstm = (32768 + 8192 + 512) * 4;           // 165888 B
    cudaFuncSetAttribute(xgemm_tc, cudaFuncAttributeMaxDynamicSharedMemorySize,
                         smem_xg);
    cudaFuncSetAttribute(lstm_tc, cudaFuncAttributeMaxDynamicSharedMemorySize,
                         smem_lstm);

    prep_ih<<<4096, 256>>>(Wih);
    prep_hh<<<2048, 256>>>(Whh);

    dim3 gx(GATES / 128, (T_STEPS * BATCH) / 32);             // (16, 2048)
    xgemm_tc<<<gx, 256, smem_xg>>>(x, bih, bhh);

    lstm_tc<<<128, 256, smem_lstm>>>(dones, out_lstm, out_hidden);
}

// round 13
// speedup vs baseline: 1.6671x; 1.6369x over previous
#include <cuda_runtime.h>
#include <cuda_fp16.h>
#include <math.h>
#include <stdint.h>

#define T_STEPS 256
#define BATCH   256
#define IN_DIM  512
#define H_DIM   512
#define GATES   2048

// ---------------- device scratch -------------------------------------------
__device__ float    g_Xg[(size_t)T_STEPS * BATCH * GATES];   // x@Wih^T + b (512MB)
__device__ unsigned g_xfr[(size_t)512 * 32 * 8 * 32 * 4];    // x fp16 A-frags (64MB)
__device__ unsigned g_wfr[64 * 4 * 32 * 32 * 2];             // Wih fp16 B-frags (2MB)
__device__ unsigned g_Wph[16 * 4 * 4 * 32 * 32 * 2];         // W_hh fp16 B-frags (2MB)
__device__ unsigned g_APg[2 * 8 * 32 * 2 * 32 * 4];          // fp16 h frags, dbl-buf
__device__ unsigned g_cnt[8 * 32];                           // per-group barrier
__device__ unsigned g_gen[8 * 32];

// ---------------- helpers --------------------------------------------------
__device__ __forceinline__ float sigm(float v) { return 1.0f / (1.0f + expf(-v)); }

__device__ __forceinline__ void mma_f16(float* c, uint4 A, uint2 B) {
    asm volatile(
        "mma.sync.aligned.m16n8k16.row.col.f32.f16.f16.f32 "
        "{%0,%1,%2,%3},{%4,%5,%6,%7},{%8,%9},{%0,%1,%2,%3};"
        : "+f"(c[0]), "+f"(c[1]), "+f"(c[2]), "+f"(c[3])
        : "r"(A.x), "r"(A.y), "r"(A.z), "r"(A.w), "r"(B.x), "r"(B.y));
}

__device__ __forceinline__ unsigned atom_add_acqrel(unsigned* p, unsigned v) {
    unsigned o;
    asm volatile("atom.acq_rel.gpu.global.add.u32 %0, [%1], %2;"
                 : "=r"(o) : "l"(p), "r"(v) : "memory");
    return o;
}
__device__ __forceinline__ void st_release(unsigned* p, unsigned v) {
    asm volatile("st.release.gpu.global.u32 [%0], %1;" :: "l"(p), "r"(v) : "memory");
}
__device__ __forceinline__ unsigned ld_acquire(const unsigned* p) {
    unsigned v;
    asm volatile("ld.acquire.gpu.global.u32 %0, [%1];" : "=r"(v) : "l"(p) : "memory");
    return v;
}

// ---------------- prep: x fp32 -> fp16 mma A-fragments ----------------------
// layout: [mtile 512][kb 32][mf 8][lane 32][reg 4] u32
// reg = (row>>3)&1 | ((k>>3)&1)<<1 ; lane = ((row&7)<<2)|((k>>1)&3); half=k&1
__global__ void prep_x_frag(const float* __restrict__ x) {
    int id = blockIdx.x * blockDim.x + threadIdx.x;   // < 16777216
    int m = id >> 8, kp = id & 255;
    float2 v = ((const float2*)x)[(size_t)m * 256 + kp];
    __half2 h2 = __floats2half2_rn(v.x, v.y);
    int mtile = m >> 7, mf = (m >> 4) & 7, row = m & 15;
    int kb = kp >> 3;
    int lane = ((row & 7) << 2) | (kp & 3);
    int reg = ((row >> 3) & 1) | (((kp >> 2) & 1) << 1);
    g_xfr[((((size_t)mtile * 32 + kb) * 8 + mf) * 32 + lane) * 4 + reg] =
        *(unsigned*)&h2;
}

// ---------------- prep: Wih fp32 -> fp16 mma B-fragments --------------------
// layout: [ns 64][n8 4][kb 32][lane 32][reg 2] u32
__global__ void prep_w_frag(const float* __restrict__ Wih) {
    int id = blockIdx.x * blockDim.x + threadIdx.x;   // < 524288
    int n = id >> 8, kp = id & 255;
    float2 v = ((const float2*)Wih)[(size_t)n * 256 + kp];
    __half2 h2 = __floats2half2_rn(v.x, v.y);
    int ns = n >> 5, n8 = (n >> 3) & 3;
    int kb = kp >> 3;
    int lane = ((n & 7) << 2) | (kp & 3);
    int reg = (kp >> 2) & 1;
    g_wfr[((((size_t)ns * 4 + n8) * 32 + kb) * 32 + lane) * 2 + reg] =
        *(unsigned*)&h2;
}

// ---------------- prep: fp16 B-fragments for W_hh (lstm path) ---------------
__global__ void prep_hh(const float* __restrict__ Whh) {
    int t = blockIdx.x * blockDim.x + threadIdx.x;     // < 2^19
    int n = t >> 8, kp = t & 255, k = kp * 2;
    float2 wv = ((const float2*)Whh)[(size_t)n * 256 + kp];
    __half2 h2 = __floats2half2_rn(wv.x, wv.y);
    int g  = n >> 9, hh = n & 511;
    int ht = hh >> 5, hg = (hh >> 3) & 3;
    int kb16 = k >> 4;
    int lanei = ((n & 7) << 2) | ((k & 7) >> 1);
    int reg = (k >> 3) & 1;
    size_t bi = ((((size_t)(ht * 4 + g) * 4 + hg) * 32 + kb16) * 32 + lanei) * 2 + reg;
    g_Wph[bi] = *(unsigned*)&h2;
}

// ---------------- xgemm: fp16 mma.sync, m-stationary -------------------------
// 512 blocks; block = 128 m-rows, A frags resident in smem (128KB).
// Loops 64 n-slices of 32 cols, W frags double-buffered (2x32KB).
// warp w -> m16 strip mf=w, all 4 n8 of the slice.
#define XG_SMEM ((32768 + 2 * 8192 + 2048) * 4)   // 200KB

__global__ __launch_bounds__(256, 1) void xgemm_f16(
    const float* __restrict__ bih, const float* __restrict__ bhh)
{
    extern __shared__ float sm_dyn[];
    unsigned* As = (unsigned*)sm_dyn;                // 32768 u32
    unsigned* Wb[2] = {As + 32768, As + 32768 + 8192};
    float* bias = (float*)(As + 32768 + 16384);      // 2048 f32

    const int tid = threadIdx.x, lane = tid & 31, w = tid >> 5;
    const int m0 = blockIdx.x * 128;

    // stage A fragments (verbatim copy), W slice 0, bias
    {
        const uint4* asrc = (const uint4*)g_xfr + (size_t)blockIdx.x * 8192;
        uint4* adst = (uint4*)As;
        #pragma unroll
        for (int i = 0; i < 32; i++) adst[tid + i * 256] = __ldg(asrc + tid + i * 256);
        const uint4* wsrc = (const uint4*)g_wfr;
        uint4* wdst = (uint4*)Wb[0];
        #pragma unroll
        for (int i = 0; i < 8; i++) wdst[tid + i * 256] = __ldg(wsrc + tid + i * 256);
        #pragma unroll
        for (int i = 0; i < 8; i++) {
            int n = tid + i * 256;
            bias[n] = __ldg(&bih[n]) + __ldg(&bhh[n]);
        }
    }
    __syncthreads();

    const int r = m0 + w * 16 + (lane >> 2);
    const int cb = (lane & 3) * 2;

    for (int i = 0; i < 64; i++) {
        const int cur = i & 1;
        // prefetch next W slice into the other buffer
        if (i + 1 < 64) {
            const uint4* ws = (const uint4*)g_wfr + (size_t)(i + 1) * 2048;
            uint4* wd = (uint4*)Wb[cur ^ 1];
            #pragma unroll
            for (int j = 0; j < 8; j++) wd[tid + j * 256] = __ldg(ws + tid + j * 256);
        }

        float acc[4][4] = {};
        const unsigned* Wc = Wb[cur];
        #pragma unroll 4
        for (int kb = 0; kb < 32; kb++) {
            uint4 A = *(const uint4*)&As[((kb * 8 + w) * 32 + lane) * 4];
            #pragma unroll
            for (int n8 = 0; n8 < 4; n8++) {
                uint2 B = *(const uint2*)&Wc[((n8 * 32 + kb) * 32 + lane) * 2];
                mma_f16(acc[n8], A, B);
            }
        }

        // epilogue: +bias, streaming store (layout of g_Xg unchanged)
        const int c0 = i * 32 + cb;
        #pragma unroll
        for (int n8 = 0; n8 < 4; n8++) {
            int c = c0 + n8 * 8;
            float b0 = bias[c], b1 = bias[c + 1];
            __stcs((float2*)&g_Xg[(size_t)r * GATES + c],
                   make_float2(acc[n8][0] + b0, acc[n8][1] + b1));
            __stcs((float2*)&g_Xg[(size_t)(r + 8) * GATES + c],
                   make_float2(acc[n8][2] + b0, acc[n8][3] + b1));
        }
        __syncthreads();
    }
}

// ---------------- persistent LSTM recurrence (unchanged, known-good) --------
__global__ __launch_bounds__(256, 1) void lstm_tc(
    const int*  __restrict__ dones,
    float* __restrict__ out_lstm,       // [T,B,H]
    float* __restrict__ out_hidden)     // [T,2,B,H]
{
    extern __shared__ float sm_dyn[];
    unsigned* Ws  = (unsigned*)sm_dyn;          // 32768 u32 (128KB)
    unsigned* APs = Ws + 32768;                 // 8192 u32  (32KB)
    unsigned* Stg = APs + 8192;                 // 512 u32   (2KB)

    const int tid = threadIdx.x, lane = tid & 31, w = tid >> 5;
    const int ht = blockIdx.x & 15, bt = blockIdx.x >> 4;
    const int hh0 = ht * 32, b0 = bt * 32;
    const int mh = w >> 2, hg = w & 3;

    const int r0 = b0 + mh * 16 + (lane >> 2);
    const int r1 = r0 + 8;
    const int c0 = hh0 + hg * 8 + (lane & 3) * 2;

    {
        const uint4* src = (const uint4*)(g_Wph + (size_t)ht * 32768);
        uint4* dst = (uint4*)Ws;
        #pragma unroll
        for (int i = 0; i < 32; i++) dst[tid + i * 256] = src[tid + i * 256];
    }
    __syncthreads();

    unsigned* cnt = &g_cnt[bt * 32];
    unsigned* gen = &g_gen[bt * 32];
    const unsigned gbase = ld_acquire(gen);

    const int slot = (((hg >> 1) * 2 + mh) * 128) + lane * 4 + ((hg & 1) << 1);

    float h_st[4] = {0.f,0.f,0.f,0.f};
    float c_st[4] = {0.f,0.f,0.f,0.f};
    float keep0 = 1.0f - (float)__ldg(&dones[r0]);
    float keep1 = 1.0f - (float)__ldg(&dones[r1]);

    for (int st = 0; st < T_STEPS; st++) {
        const float* xgr0 = g_Xg + ((size_t)st * BATCH + r0) * GATES + c0;
        const float* xgr1 = g_Xg + ((size_t)st * BATCH + r1) * GATES + c0;
        float2 xv0[4], xv1[4];
        #pragma unroll
        for (int g = 0; g < 4; g++) {
            xv0[g] = __ldcs((const float2*)(xgr0 + g * H_DIM));
            xv1[g] = __ldcs((const float2*)(xgr1 + g * H_DIM));
        }

        float acc[4][4] = {};
        if (st > 0) {
            const uint4* asrc = (const uint4*)(g_APg + ((size_t)(st & 1) * 8 + bt) * 8192);
            uint4* adst = (uint4*)APs;
            #pragma unroll
            for (int i = 0; i < 8; i++)
                adst[tid + i * 256] = __ldcg(asrc + tid + i * 256);
            __syncthreads();

            #pragma unroll 4
            for (int kb = 0; kb < 32; kb++) {
                uint4 A = *(const uint4*)&APs[((kb * 2 + mh) * 32 + lane) * 4];
                #pragma unroll
                for (int g = 0; g < 4; g++) {
                    uint2 B = *(const uint2*)&Ws[(((g * 4 + hg) * 32 + kb) * 32 + lane) * 2];
                    mma_f16(acc[g], A, B);
                }
            }
        }

        float xa[4][4];
        #pragma unroll
        for (int g = 0; g < 4; g++) {
            xa[g][0] = xv0[g].x; xa[g][1] = xv0[g].y;
            xa[g][2] = xv1[g].x; xa[g][3] = xv1[g].y;
        }
        float hp[4], cp[4];
        #pragma unroll
        for (int i = 0; i < 4; i++) {
            float k_ = (i < 2) ? keep0 : keep1;
            float hpv = h_st[i] * k_;
            float cpv = c_st[i] * k_;
            float ii = sigm(acc[0][i] + xa[0][i]);
            float ff = sigm(acc[1][i] + xa[1][i]);
            float gg = tanhf(acc[2][i] + xa[2][i]);
            float oo = sigm(acc[3][i] + xa[3][i]);
            float cn = ff * cpv + ii * gg;
            float hn = oo * tanhf(cn);
            h_st[i] = hn; c_st[i] = cn; hp[i] = hpv; cp[i] = cpv;
        }

        bool not_last = (st < T_STEPS - 1);
        unsigned tgt = gbase + (unsigned)st + 1u;
        if (not_last) {
            float kn0 = 1.0f - (float)__ldg(&dones[(st + 1) * BATCH + r0]);
            float kn1 = 1.0f - (float)__ldg(&dones[(st + 1) * BATCH + r1]);
            __half2 w0 = __floats2half2_rn(h_st[0] * kn0, h_st[1] * kn0);
            __half2 w1 = __floats2half2_rn(h_st[2] * kn1, h_st[3] * kn1);
            Stg[slot]     = *(unsigned*)&w0;
            Stg[slot + 1] = *(unsigned*)&w1;
            keep0 = kn0; keep1 = kn1;
            __syncthreads();
            unsigned* apd = g_APg + (((size_t)((st + 1) & 1) * 8 + bt) * 8192)
                          + (size_t)ht * 512;
            if (tid < 128)
                ((uint4*)apd)[tid] = ((const uint4*)Stg)[tid];
            __syncthreads();
            if (tid == 0) {
                if (atom_add_acqrel(cnt, 1u) == 15u) {
                    *cnt = 0;
                    st_release(gen, tgt);
                }
            }
        }

        const size_t ob0 = (size_t)r0 * H_DIM + c0;
        const size_t ob1 = (size_t)r1 * H_DIM + c0;
        const size_t hb  = (size_t)st * 2 * BATCH * H_DIM;
        const size_t lb  = (size_t)st * BATCH * H_DIM;
        __stcs((float2*)&out_hidden[hb + ob0],                       make_float2(hp[0], hp[1]));
        __stcs((float2*)&out_hidden[hb + ob1],                       make_float2(hp[2], hp[3]));
        __stcs((float2*)&out_hidden[hb + (size_t)BATCH*H_DIM + ob0], make_float2(cp[0], cp[1]));
        __stcs((float2*)&out_hidden[hb + (size_t)BATCH*H_DIM + ob1], make_float2(cp[2], cp[3]));
        __stcs((float2*)&out_lstm[lb + ob0],                         make_float2(h_st[0], h_st[1]));
        __stcs((float2*)&out_lstm[lb + ob1],                         make_float2(h_st[2], h_st[3]));

        if (not_last) {
            if (tid == 0) {
                while (ld_acquire(gen) != tgt) { }
            }
            __syncthreads();
        }
    }
}

// ---------------- launch ----------------------------------------------------
extern "C" void kernel_launch(void* const* d_in, const int* in_sizes, int n_in,
                              void* d_out, int out_size) {
    const float* x     = (const float*)d_in[0];
    const int*   dones = (const int*)  d_in[1];
    const float* Wih   = (const float*)d_in[2];
    const float* Whh   = (const float*)d_in[3];
    const float* bih   = (const float*)d_in[4];
    const float* bhh   = (const float*)d_in[5];

    float* out_lstm   = (float*)d_out;
    float* out_hidden = out_lstm + (size_t)T_STEPS * BATCH * H_DIM;

    const int smem_xg   = XG_SMEM;                            // 204800 B
    const int smem_lstm = (32768 + 8192 + 512) * 4;           // 165888 B
    cudaFuncSetAttribute(xgemm_f16, cudaFuncAttributeMaxDynamicSharedMemorySize,
                         smem_xg);
    cudaFuncSetAttribute(lstm_tc, cudaFuncAttributeMaxDynamicSharedMemorySize,
                         smem_lstm);

    prep_x_frag<<<65536, 256>>>(x);
    prep_w_frag<<<2048, 256>>>(Wih);
    prep_hh<<<2048, 256>>>(Whh);

    xgemm_f16<<<512, 256, smem_xg>>>(bih, bhh);

    lstm_tc<<<128, 256, smem_lstm>>>(dones, out_lstm, out_hidden);
}